// round 1
// baseline (speedup 1.0000x reference)
#include <cuda_runtime.h>

#define NN 8192
#define DD 128
#define PP 256
#define KK 256
#define DEG 32
#define FF 16
#define TEMP 0.07f

// Scratch (no allocations allowed -> __device__ globals)
__device__ float g_zq[DD];
__device__ float g_znb[PP * DD];
__device__ float g_znx[DEG * DD];
__device__ float g_tenx[DEG];
__device__ float g_pos[PP];
__device__ float g_align[PP];
__device__ float g_core[PP];
__device__ float g_neg[KK];

__device__ __forceinline__ float warp_sum(float v) {
#pragma unroll
    for (int o = 16; o; o >>= 1) v += __shfl_xor_sync(0xffffffffu, v, o);
    return v;
}

// ---------------------------------------------------------------------------
// Kernel 1: normalize needed z rows into scratch + time encodings for N(q)
// grid = 1 + PP + DEG blocks, 128 threads
// ---------------------------------------------------------------------------
__global__ void prep_kernel(const float* __restrict__ z,
                            const float* __restrict__ edge_times,
                            const float* __restrict__ ct,
                            const float* __restrict__ omega,
                            const float* __restrict__ phi,
                            const int* __restrict__ qidx,
                            const int* __restrict__ nbr_idxs,
                            const int* __restrict__ neighbors) {
    int b = blockIdx.x, t = threadIdx.x;
    int q = qidx[0];
    int row;
    float* dst;
    if (b == 0) {
        row = q; dst = g_zq;
    } else if (b <= PP) {
        row = nbr_idxs[b - 1]; dst = g_znb + (b - 1) * DD;
    } else {
        int j = b - PP - 1;
        row = neighbors[q * DEG + j]; dst = g_znx + j * DD;
    }
    float v = z[(long long)row * DD + t];
    float s = warp_sum(v * v);
    __shared__ float ws[4];
    if ((t & 31) == 0) ws[t >> 5] = s;
    __syncthreads();
    float tot = ws[0] + ws[1] + ws[2] + ws[3];
    dst[t] = v * rsqrtf(fmaxf(tot, 1e-24f));

    if (b == 0 && t < DEG) {
        int nq = neighbors[q * DEG + t];
        float dt = ct[0] - edge_times[(long long)q * NN + nq];
        float te = omega[0] * dt + phi[0];
#pragma unroll
        for (int f = 1; f < FF; f++) te += sinf(omega[f] * dt + phi[f]);
        g_tenx[t] = te;
    }
}

// ---------------------------------------------------------------------------
// Kernel 2: per-neighbor terms + losses; negatives in tail blocks
// grid = PP + KK/8 = 288 blocks, 256 threads (8 warps)
// ---------------------------------------------------------------------------
__global__ void main_kernel(const float* __restrict__ z,
                            const float* __restrict__ edge_times,
                            const float* __restrict__ ct,
                            const float* __restrict__ core,
                            const float* __restrict__ omega,
                            const float* __restrict__ phi,
                            const int* __restrict__ qidx,
                            const int* __restrict__ neg_idxs,
                            const int* __restrict__ nbr_idxs,
                            const int* __restrict__ neighbors) {
    __shared__ float s_zq[DD];
    __shared__ float s_zi[DD];
    __shared__ float s_mu1[DEG], s_mu2[DEG], s_te2[DEG];
    __shared__ float s_red[8];
    __shared__ float s_t12[2];

    int t = threadIdx.x, lane = t & 31, warp = t >> 5;
    int b = blockIdx.x;

    if (t < DD) s_zq[t] = g_zq[t];
    __syncthreads();

    if (b < PP) {
        int nbr = nbr_idxs[b];
        if (t < DD) s_zi[t] = g_znb[b * DD + t];
        __syncthreads();
        float ct0 = ct[0];

        // ---- term1: mu over N(q) rows (already normalized in scratch) ----
#pragma unroll
        for (int it = 0; it < 4; ++it) {
            int j = warp + 8 * it;
            const float* znx = g_znx + j * DD;
            float acc = 0.f;
#pragma unroll
            for (int k = 0; k < 4; k++) {
                int idx = lane + 32 * k;
                float d = s_zi[idx] - znx[idx];
                acc += d * d;
            }
            acc = warp_sum(acc);
            if (lane == 0) s_mu1[j] = -acc;
        }

        // ---- term2: mu over N(y) rows (normalize on the fly) + time enc ----
        long long ebase = (long long)nbr * NN;
#pragma unroll
        for (int it = 0; it < 4; ++it) {
            int j = warp + 8 * it;
            int y = neighbors[nbr * DEG + j];
            const float* zy = z + (long long)y * DD;
            float v0 = zy[lane], v1 = zy[lane + 32], v2 = zy[lane + 64], v3 = zy[lane + 96];
            float ss = warp_sum(v0 * v0 + v1 * v1 + v2 * v2 + v3 * v3);
            float rinv = rsqrtf(fmaxf(ss, 1e-24f));
            float d0 = v0 * rinv - s_zq[lane];
            float d1 = v1 * rinv - s_zq[lane + 32];
            float d2 = v2 * rinv - s_zq[lane + 64];
            float d3 = v3 * rinv - s_zq[lane + 96];
            float acc = warp_sum(d0 * d0 + d1 * d1 + d2 * d2 + d3 * d3);
            if (lane == 0) {
                s_mu2[j] = -acc;
                float dt = ct0 - edge_times[ebase + y];
                float te = omega[0] * dt + phi[0];
#pragma unroll
                for (int f = 1; f < FF; f++) te += sinf(omega[f] * dt + phi[f]);
                s_te2[j] = te;
            }
        }

        // ---- mu_xy ----
        float mx = 0.f;
        if (t < DD) {
            float d = s_zi[t] - s_zq[t];
            mx = d * d;
        }
        mx = warp_sum(mx);
        if (lane == 0) s_red[warp] = mx;
        __syncthreads();  // also publishes s_mu1/s_mu2/s_te2

        // ---- softmaxes (warp 0 -> term1, warp 1 -> term2), exact ref math ----
        if (warp < 2) {
            float mu = (warp == 0) ? s_mu1[lane] : s_mu2[lane];
            float te = (warp == 0) ? g_tenx[lane] : s_te2[lane];
            float w = expf(mu / TEMP - te);
            float S = warp_sum(w);
            float a = w / (S + 1e-8f);
            float term = warp_sum(a * mu);
            if (lane == 0) s_t12[warp] = term;
        }
        __syncthreads();

        if (t == 0) {
            float mu_xy = -(s_red[0] + s_red[1] + s_red[2] + s_red[3]);
            float term1 = s_t12[0], term2 = s_t12[1];
            float sg = 1.f / (1.f + expf(-mu_xy));
            g_pos[b] = -logf(sg + 1e-8f);
            float dd = term1 + term2;  // lambda_T - lambda_S
            float ad = fabsf(dd);
            g_align[b] = (ad < 1.f) ? 0.5f * dd * dd : (ad - 0.5f);
            float dc = core[nbr] - core[qidx[0]];
            g_core[b] = dc * dc;
        }
    } else {
        // ---- negatives: 8 per block, one per warp ----
        int k = (b - PP) * 8 + warp;
        int y = neg_idxs[k];
        const float* zy = z + (long long)y * DD;
        float v0 = zy[lane], v1 = zy[lane + 32], v2 = zy[lane + 64], v3 = zy[lane + 96];
        float ss = warp_sum(v0 * v0 + v1 * v1 + v2 * v2 + v3 * v3);
        float rinv = rsqrtf(fmaxf(ss, 1e-24f));
        float d0 = v0 * rinv - s_zq[lane];
        float d1 = v1 * rinv - s_zq[lane + 32];
        float d2 = v2 * rinv - s_zq[lane + 64];
        float d3 = v3 * rinv - s_zq[lane + 96];
        float acc = warp_sum(d0 * d0 + d1 * d1 + d2 * d2 + d3 * d3);
        if (lane == 0) {
            float mu = -acc;
            float sg = 1.f / (1.f + expf(-mu));
            g_neg[k] = -logf(1.f - sg + 1e-8f);
        }
    }
}

// ---------------------------------------------------------------------------
// Kernel 3: deterministic final reduction -> scalar
// ---------------------------------------------------------------------------
__global__ void reduce_kernel(float* __restrict__ out) {
    int t = threadIdx.x, lane = t & 31, warp = t >> 5;
    __shared__ float sm[8];
    float vals[4] = {g_pos[t], g_neg[t], g_core[t], g_align[t]};
    float sums[4] = {0.f, 0.f, 0.f, 0.f};
#pragma unroll
    for (int a = 0; a < 4; a++) {
        float s = warp_sum(vals[a]);
        if (lane == 0) sm[warp] = s;
        __syncthreads();
        if (t == 0) {
            float tot = 0.f;
#pragma unroll
            for (int w = 0; w < 8; w++) tot += sm[w];
            sums[a] = tot;
        }
        __syncthreads();
    }
    if (t == 0) {
        float pos_loss = sums[0] / (float)PP;
        float neg_loss = sums[1] / (float)KK;
        float core_loss = sums[2] / (float)PP;
        float align = sums[3] / (float)PP;
        out[0] = (pos_loss + neg_loss) + 0.1f * core_loss + 0.1f * align;
    }
}

// ---------------------------------------------------------------------------
// Inputs (metadata order):
// 0 z [N*D] f32, 1 edge_times [N*N] f32, 2 current_time [1] f32,
// 3 core_values [N] f32, 4 omega [F] f32, 5 phi [F] f32,
// 6 query_idx [1] i32, 7 neg_idxs [K] i32, 8 neighbor_idxs [P] i32,
// 9 neighbors [N*DEG] i32. Output: [1] f32.
// ---------------------------------------------------------------------------
extern "C" void kernel_launch(void* const* d_in, const int* in_sizes, int n_in,
                              void* d_out, int out_size) {
    const float* z     = (const float*)d_in[0];
    const float* et    = (const float*)d_in[1];
    const float* ct    = (const float*)d_in[2];
    const float* core  = (const float*)d_in[3];
    const float* omega = (const float*)d_in[4];
    const float* phi   = (const float*)d_in[5];
    const int*   qidx  = (const int*)d_in[6];
    const int*   negi  = (const int*)d_in[7];
    const int*   nbri  = (const int*)d_in[8];
    const int*   nbrs  = (const int*)d_in[9];

    prep_kernel<<<1 + PP + DEG, DD>>>(z, et, ct, omega, phi, qidx, nbri, nbrs);
    main_kernel<<<PP + KK / 8, 256>>>(z, et, ct, core, omega, phi, qidx, negi, nbri, nbrs);
    reduce_kernel<<<1, 256>>>((float*)d_out);
}

// round 2
// speedup vs baseline: 2.3542x; 2.3542x over previous
#include <cuda_runtime.h>

#define NN 8192
#define DD 128
#define PP 256
#define KK 256
#define DEG 32
#define FF 16
#define TEMP 0.07f

// Scratch (__device__ globals; no allocations allowed)
__device__ float g_pos[PP];
__device__ float g_align[PP];
__device__ float g_core[PP];
__device__ float g_neg[KK];
__device__ int   g_count = 0;

__device__ __forceinline__ float warp_sum(float v) {
#pragma unroll
    for (int o = 16; o; o >>= 1) v += __shfl_xor_sync(0xffffffffu, v, o);
    return v;
}

// ---------------------------------------------------------------------------
// Single fused kernel.
// grid = PP + KK/8 = 288 blocks x 256 threads.
//   blocks [0,PP):   one neighbor i each -> term1, term2, mu_xy, losses
//   blocks [PP,288): 8 negatives each (one per warp)
// Last block (atomic arrival counter) does the deterministic final reduction.
// ---------------------------------------------------------------------------
__global__ void __launch_bounds__(256)
fused_kernel(const float* __restrict__ z,
             const float* __restrict__ et,
             const float* __restrict__ ct,
             const float* __restrict__ core,
             const float* __restrict__ omega,
             const float* __restrict__ phi,
             const int* __restrict__ qidx,
             const int* __restrict__ neg_idxs,
             const int* __restrict__ nbr_idxs,
             const int* __restrict__ neighbors,
             float* __restrict__ out) {
    __shared__ float s_zq[DD], s_zi[DD];
    __shared__ int   s_nq[DEG], s_ny[DEG];
    __shared__ float s_dt[2 * DEG], s_te[2 * DEG];
    __shared__ float s_mu1[DEG], s_mu2[DEG];
    __shared__ float s_om[FF], s_ph[FF];
    __shared__ float s_ws[8];
    __shared__ float s_red[8];
    __shared__ float s_t12[2];
    __shared__ bool  s_isLast;

    const int t = threadIdx.x, lane = t & 31, warp = t >> 5;
    const int b = blockIdx.x;
    const bool isMain = (b < PP);

    const int q = qidx[0];
    const int nbr = isMain ? nbr_idxs[b] : 0;
    const float ct0 = ct[0];

    // prefetch core scalars (hide DRAM latency behind the rest)
    float cq = 0.f, ci = 0.f;
    if (t == 0 && isMain) { cq = core[q]; ci = core[nbr]; }

    // ---- Phase A: issue all front loads ----
    float vq = 0.f, vi = 0.f;
    if (t < DD) vq = z[(long long)q * DD + t];
    if (t >= DD && isMain) vi = z[(long long)nbr * DD + (t - DD)];
    if (t < FF) s_om[t] = omega[t];
    else if (t < 2 * FF) s_ph[t - FF] = phi[t - FF];
    if (isMain) {
        if (t >= 2 * FF && t < 2 * FF + DEG) s_nq[t - 2 * FF] = neighbors[q * DEG + (t - 2 * FF)];
        else if (t >= 2 * FF + DEG && t < 2 * FF + 2 * DEG)
            s_ny[t - 2 * FF - DEG] = neighbors[nbr * DEG + (t - 2 * FF - DEG)];
    }

    // ---- normalize z_q (warps 0-3) and z_i (warps 4-7) ----
    {
        float s = warp_sum(warp < 4 ? vq * vq : vi * vi);
        if (lane == 0) s_ws[warp] = s;
    }
    __syncthreads();
    const float totq = s_ws[0] + s_ws[1] + s_ws[2] + s_ws[3];
    const float rq = rsqrtf(fmaxf(totq, 1e-24f));
    const float na_q = totq * rq * rq;            // ~1, Σ s_zq^2
    float na_i = 0.f;
    if (t < DD) s_zq[t] = vq * rq;
    if (isMain) {
        const float toti = s_ws[4] + s_ws[5] + s_ws[6] + s_ws[7];
        const float ri = rsqrtf(fmaxf(toti, 1e-24f));
        na_i = toti * ri * ri;
        if (t >= DD) s_zi[t - DD] = vi * ri;
    }
    __syncthreads();

    if (isMain) {
        // ---- Phase B: gather edge_times for both neighborhoods ----
        if (t < DEG) s_dt[t] = ct0 - et[(long long)q * NN + s_nq[t]];
        else if (t < 2 * DEG) s_dt[t] = ct0 - et[(long long)nbr * NN + s_ny[t - DEG]];
        __syncthreads();

        // ---- Phase C: 64 time encodings, 4 threads each ----
        {
            const int e = t >> 2, sub = t & 3;
            const float dt = s_dt[e];
            float p = 0.f;
#pragma unroll
            for (int k = 0; k < 4; k++) {
                int f = 1 + sub + 4 * k;
                if (f < FF) p += __sinf(s_om[f] * dt + s_ph[f]);
            }
            p += __shfl_xor_sync(0xffffffffu, p, 1);
            p += __shfl_xor_sync(0xffffffffu, p, 2);
            if (sub == 0) s_te[e] = s_om[0] * dt + s_ph[0] + p;
        }

        // ---- row loop: each warp handles j = warp + 8*it, both terms ----
#pragma unroll
        for (int it = 0; it < 4; ++it) {
            const int j = warp + 8 * it;
            const float* zr1 = z + (long long)s_nq[j] * DD;  // N(q) row (term1)
            const float* zr2 = z + (long long)s_ny[j] * DD;  // N(y) row (term2)
            float n1 = 0.f, d1 = 0.f, n2 = 0.f, d2 = 0.f;
#pragma unroll
            for (int k = 0; k < 4; k++) {
                const int idx = lane + 32 * k;
                const float a = zr1[idx];
                const float c = zr2[idx];
                n1 += a * a; d1 += s_zi[idx] * a;
                n2 += c * c; d2 += s_zq[idx] * c;
            }
            n1 = warp_sum(n1); d1 = warp_sum(d1);
            n2 = warp_sum(n2); d2 = warp_sum(d2);
            if (lane == 0) {
                const float r1 = rsqrtf(fmaxf(n1, 1e-24f));
                s_mu1[j] = -(na_i + n1 * r1 * r1 - 2.f * r1 * d1);
                const float r2 = rsqrtf(fmaxf(n2, 1e-24f));
                s_mu2[j] = -(na_q + n2 * r2 * r2 - 2.f * r2 * d2);
            }
        }

        // ---- mu_xy = -||z_i - z_q||^2 (direct form) ----
        {
            float mx = 0.f;
            if (t < DD) {
                const float d = s_zi[t] - s_zq[t];
                mx = d * d;
            }
            mx = warp_sum(mx);
            if (lane == 0) s_red[warp] = mx;
        }
        __syncthreads();  // publishes s_mu1/s_mu2/s_te/s_red

        // ---- softmaxes: warp0 -> term1, warp1 -> term2 (exact ref math) ----
        if (warp < 2) {
            const float mu = (warp == 0) ? s_mu1[lane] : s_mu2[lane];
            const float te = (warp == 0) ? s_te[lane] : s_te[DEG + lane];
            const float w = expf(mu / TEMP - te);
            const float S = warp_sum(w);
            const float a = w / (S + 1e-8f);
            const float term = warp_sum(a * mu);
            if (lane == 0) s_t12[warp] = term;
        }
        __syncthreads();

        if (t == 0) {
            const float mu_xy = -(s_red[0] + s_red[1] + s_red[2] + s_red[3]);
            const float sg = 1.f / (1.f + expf(-mu_xy));
            g_pos[b] = -logf(sg + 1e-8f);
            const float dd = s_t12[0] + s_t12[1];   // lambda_T - lambda_S
            const float ad = fabsf(dd);
            g_align[b] = (ad < 1.f) ? 0.5f * dd * dd : (ad - 0.5f);
            const float dc = ci - cq;
            g_core[b] = dc * dc;
        }
    } else {
        // ---- negatives: one per warp ----
        const int k = (b - PP) * 8 + warp;
        const int y = neg_idxs[k];
        const float* zy = z + (long long)y * DD;
        float nv = 0.f, dv = 0.f;
#pragma unroll
        for (int kk = 0; kk < 4; kk++) {
            const int idx = lane + 32 * kk;
            const float v = zy[idx];
            nv += v * v; dv += s_zq[idx] * v;
        }
        nv = warp_sum(nv); dv = warp_sum(dv);
        if (lane == 0) {
            const float rv = rsqrtf(fmaxf(nv, 1e-24f));
            const float mu = -(na_q + nv * rv * rv - 2.f * rv * dv);
            const float sg = 1.f / (1.f + expf(-mu));
            g_neg[k] = -logf(1.f - sg + 1e-8f);
        }
    }

    // ---- completion: last-arriving block reduces deterministically ----
    __threadfence();
    __syncthreads();
    if (t == 0) {
        const int c = atomicAdd(&g_count, 1);
        s_isLast = (c == (int)gridDim.x - 1);
    }
    __syncthreads();
    if (s_isLast) {
        __threadfence();
        const float vals[4] = {g_pos[t], g_neg[t], g_core[t], g_align[t]};
        float sums[4];
#pragma unroll
        for (int a = 0; a < 4; a++) {
            float s = warp_sum(vals[a]);
            if (lane == 0) s_ws[warp] = s;
            __syncthreads();
            float tot = 0.f;
#pragma unroll
            for (int w = 0; w < 8; w++) tot += s_ws[w];
            sums[a] = tot;
            __syncthreads();
        }
        if (t == 0) {
            const float pos_loss = sums[0] / (float)PP;
            const float neg_loss = sums[1] / (float)KK;
            const float core_loss = sums[2] / (float)PP;
            const float align = sums[3] / (float)PP;
            out[0] = (pos_loss + neg_loss) + 0.1f * core_loss + 0.1f * align;
            g_count = 0;  // reset for next graph replay
        }
    }
}

// ---------------------------------------------------------------------------
// Inputs (metadata order):
// 0 z [N*D] f32, 1 edge_times [N*N] f32, 2 current_time [1] f32,
// 3 core_values [N] f32, 4 omega [F] f32, 5 phi [F] f32,
// 6 query_idx [1] i32, 7 neg_idxs [K] i32, 8 neighbor_idxs [P] i32,
// 9 neighbors [N*DEG] i32. Output: [1] f32.
// ---------------------------------------------------------------------------
extern "C" void kernel_launch(void* const* d_in, const int* in_sizes, int n_in,
                              void* d_out, int out_size) {
    const float* z     = (const float*)d_in[0];
    const float* et    = (const float*)d_in[1];
    const float* ct    = (const float*)d_in[2];
    const float* core  = (const float*)d_in[3];
    const float* omega = (const float*)d_in[4];
    const float* phi   = (const float*)d_in[5];
    const int*   qidx  = (const int*)d_in[6];
    const int*   negi  = (const int*)d_in[7];
    const int*   nbri  = (const int*)d_in[8];
    const int*   nbrs  = (const int*)d_in[9];

    fused_kernel<<<PP + KK / 8, 256>>>(z, et, ct, core, omega, phi,
                                       qidx, negi, nbri, nbrs, (float*)d_out);
}